// round 1
// baseline (speedup 1.0000x reference)
#include <cuda_runtime.h>
#include <cuda_bf16.h>

// Problem constants
#define NP        20        // prototypes per user
#define D         64        // feature dim
#define NROWS     16384
#define EPS       1e-12f

#define ROWS_PER_WARP 4
#define WARPS_PER_BLK 8
#define THREADS       (WARPS_PER_BLK * 32)
#define ROWS_PER_BLK  (WARPS_PER_BLK * ROWS_PER_WARP)   // 32
#define NBLOCKS       (NROWS / ROWS_PER_BLK)            // 512

__device__ __forceinline__ float warp_sum(float v) {
    #pragma unroll
    for (int m = 16; m >= 1; m >>= 1)
        v += __shfl_xor_sync(0xFFFFFFFFu, v, m);
    return v;
}

__global__ __launch_bounds__(THREADS)
void user_memory_kernel(const int* __restrict__ uidx,
                        const float* __restrict__ x,
                        const float* __restrict__ proto,
                        const float* __restrict__ W,
                        const float* __restrict__ b,
                        float* __restrict__ out)
{
    __shared__ float Ws[D][D + 1];                         // stride 65: conflict-free column reads
    __shared__ float xs[WARPS_PER_BLK][ROWS_PER_WARP][D];  // per-warp staged x rows

    const int tid  = threadIdx.x;
    const int warp = tid >> 5;
    const int lane = tid & 31;

    // Cooperative load of W into smem (4096 elements, 256 threads -> 16 iters)
    #pragma unroll
    for (int i = tid; i < D * D; i += THREADS) {
        int d = i >> 6, k = i & 63;
        Ws[d][k] = W[i];
    }

    const int rowbase = (blockIdx.x * WARPS_PER_BLK + warp) * ROWS_PER_WARP;

    // Stage x rows for this warp (float2 per lane per row, coalesced)
    #pragma unroll
    for (int r = 0; r < ROWS_PER_WARP; ++r) {
        float2 v = ((const float2*)(x + (size_t)(rowbase + r) * D))[lane];
        ((float2*)&xs[warp][r][0])[lane] = v;
    }
    __syncthreads();

    // Bias for this thread's two output dims (d = lane, lane+32)
    const float b0 = __ldg(&b[lane]);
    const float b1 = __ldg(&b[lane + 32]);

    // ---- matvec: h[r][d] = b[d] + sum_k x[r][k] * W[d][k] ----
    float h0[ROWS_PER_WARP], h1[ROWS_PER_WARP];
    #pragma unroll
    for (int r = 0; r < ROWS_PER_WARP; ++r) { h0[r] = b0; h1[r] = b1; }

    #pragma unroll 8
    for (int k = 0; k < D; ++k) {
        float w0 = Ws[lane][k];        // bank (lane+k)%32  -> conflict-free
        float w1 = Ws[lane + 32][k];   // same banks        -> conflict-free
        #pragma unroll
        for (int r = 0; r < ROWS_PER_WARP; ++r) {
            float xv = xs[warp][r][k]; // broadcast
            h0[r] = fmaf(xv, w0, h0[r]);
            h1[r] = fmaf(xv, w1, h1[r]);
        }
    }

    // ---- normalize h -> z ----
    float z0[ROWS_PER_WARP], z1[ROWS_PER_WARP];
    {
        float nn[ROWS_PER_WARP];
        #pragma unroll
        for (int r = 0; r < ROWS_PER_WARP; ++r)
            nn[r] = h0[r] * h0[r] + h1[r] * h1[r];
        #pragma unroll
        for (int m = 16; m >= 1; m >>= 1) {
            #pragma unroll
            for (int r = 0; r < ROWS_PER_WARP; ++r)
                nn[r] += __shfl_xor_sync(0xFFFFFFFFu, nn[r], m);
        }
        #pragma unroll
        for (int r = 0; r < ROWS_PER_WARP; ++r) {
            float inv = 1.0f / fmaxf(sqrtf(nn[r]), EPS);
            z0[r] = h0[r] * inv;
            z1[r] = h1[r] * inv;
        }
    }

    // ---- anchors: s = sum_p normalize(a_p) ----
    const float* ap[ROWS_PER_WARP];
    #pragma unroll
    for (int r = 0; r < ROWS_PER_WARP; ++r) {
        int u = __ldg(&uidx[rowbase + r]);
        ap[r] = proto + (size_t)u * (NP * D);
    }

    float s0[ROWS_PER_WARP] = {0.f, 0.f, 0.f, 0.f};
    float s1[ROWS_PER_WARP] = {0.f, 0.f, 0.f, 0.f};

    #pragma unroll 2
    for (int p = 0; p < NP; ++p) {
        float a0[ROWS_PER_WARP], a1[ROWS_PER_WARP], nn[ROWS_PER_WARP];
        const int off = p * D;
        #pragma unroll
        for (int r = 0; r < ROWS_PER_WARP; ++r) {
            a0[r] = __ldg(ap[r] + off + lane);        // coalesced 128B
            a1[r] = __ldg(ap[r] + off + lane + 32);   // coalesced 128B
        }
        #pragma unroll
        for (int r = 0; r < ROWS_PER_WARP; ++r)
            nn[r] = a0[r] * a0[r] + a1[r] * a1[r];
        #pragma unroll
        for (int m = 16; m >= 1; m >>= 1) {
            #pragma unroll
            for (int r = 0; r < ROWS_PER_WARP; ++r)
                nn[r] += __shfl_xor_sync(0xFFFFFFFFu, nn[r], m);
        }
        #pragma unroll
        for (int r = 0; r < ROWS_PER_WARP; ++r) {
            float inv = 1.0f / fmaxf(sqrtf(nn[r]), EPS);
            s0[r] = fmaf(a0[r], inv, s0[r]);
            s1[r] = fmaf(a1[r], inv, s1[r]);
        }
    }

    // ---- score = z . s ----
    #pragma unroll
    for (int r = 0; r < ROWS_PER_WARP; ++r) {
        float d = z0[r] * s0[r] + z1[r] * s1[r];
        d = warp_sum(d);
        if (lane == 0)
            out[rowbase + r] = d;
    }
}

extern "C" void kernel_launch(void* const* d_in, const int* in_sizes, int n_in,
                              void* d_out, int out_size) {
    const int*   uidx  = (const int*)d_in[0];
    const float* x     = (const float*)d_in[1];
    const float* proto = (const float*)d_in[2];
    const float* W     = (const float*)d_in[3];
    const float* b     = (const float*)d_in[4];
    float* out = (float*)d_out;

    user_memory_kernel<<<NBLOCKS, THREADS>>>(uidx, x, proto, W, b, out);
}

// round 2
// speedup vs baseline: 1.1306x; 1.1306x over previous
#include <cuda_runtime.h>
#include <cuda_bf16.h>

#define NP      20
#define D       64
#define NROWS   16384
#define EPS2    1e-24f      // (1e-12)^2 guard under rsqrt

#define R       2                    // rows per warp
#define WPB     8                    // warps per block
#define THREADS (WPB * 32)
#define ROWSB   (WPB * R)            // 16
#define NBLOCKS (NROWS / ROWSB)      // 1024

__global__ __launch_bounds__(THREADS)
void user_memory_kernel(const int* __restrict__ uidx,
                        const float* __restrict__ x,
                        const float* __restrict__ proto,
                        const float* __restrict__ W,
                        const float* __restrict__ b,
                        float* __restrict__ out)
{
    __shared__ float Ws[D][D + 1];      // stride 65 -> conflict-free column reads
    __shared__ float xs[WPB][R][D];

    const int tid  = threadIdx.x;
    const int warp = tid >> 5;
    const int lane = tid & 31;
    const int q    = lane & 15;        // position within 16-lane half
    const int half = lane >> 4;        // which proto of the pair this half loads

    const int rowbase = (blockIdx.x * WPB + warp) * R;

    // ---- issue gather-dependent loads as early as possible ----
    const float* ap[R];
    #pragma unroll
    for (int r = 0; r < R; ++r) {
        int u = __ldg(&uidx[rowbase + r]);
        ap[r] = proto + (size_t)u * (NP * D);
    }
    // prefetch proto chunks 0 and 1 (protos 0..3) — overlaps DRAM with matvec
    float4 pa0[R], pa1[R];
    #pragma unroll
    for (int r = 0; r < R; ++r) {
        pa0[r] = __ldg((const float4*)(ap[r] + (0 * 2 + half) * D) + q);
        pa1[r] = __ldg((const float4*)(ap[r] + (1 * 2 + half) * D) + q);
    }

    // ---- stage W and x ----
    #pragma unroll
    for (int i = tid; i < D * D; i += THREADS)
        Ws[i >> 6][i & 63] = W[i];
    #pragma unroll
    for (int r = 0; r < R; ++r) {
        float2 v = ((const float2*)(x + (size_t)(rowbase + r) * D))[lane];
        ((float2*)&xs[warp][r][0])[lane] = v;
    }
    __syncthreads();

    const float b0 = __ldg(&b[lane]);
    const float b1 = __ldg(&b[lane + 32]);

    // ---- matvec: h[r][d] = b[d] + sum_k x[r][k]*W[d][k], d = lane, lane+32 ----
    float h0[R], h1[R];
    #pragma unroll
    for (int r = 0; r < R; ++r) { h0[r] = b0; h1[r] = b1; }

    #pragma unroll 8
    for (int k = 0; k < D; ++k) {
        float w0 = Ws[lane][k];
        float w1 = Ws[lane + 32][k];
        #pragma unroll
        for (int r = 0; r < R; ++r) {
            float xv = xs[warp][r][k];
            h0[r] = fmaf(xv, w0, h0[r]);
            h1[r] = fmaf(xv, w1, h1[r]);
        }
    }

    // ---- normalize h -> z (layout: dims lane, lane+32) ----
    float z0[R], z1[R];
    {
        float nn[R];
        #pragma unroll
        for (int r = 0; r < R; ++r) nn[r] = h0[r] * h0[r] + h1[r] * h1[r];
        #pragma unroll
        for (int m = 16; m >= 1; m >>= 1) {
            #pragma unroll
            for (int r = 0; r < R; ++r)
                nn[r] += __shfl_xor_sync(0xFFFFFFFFu, nn[r], m);
        }
        #pragma unroll
        for (int r = 0; r < R; ++r) {
            float inv = rsqrtf(fmaxf(nn[r], EPS2));
            z0[r] = h0[r] * inv;
            z1[r] = h1[r] * inv;
        }
    }

    // ---- permute z into float4 layout: zq[r][i] = z[dim 4q+i] ----
    float zq[R][4];
    #pragma unroll
    for (int r = 0; r < R; ++r) {
        #pragma unroll
        for (int i = 0; i < 4; ++i) {
            int src = (4 * q + i) & 31;
            float t0 = __shfl_sync(0xFFFFFFFFu, z0[r], src);
            float t1 = __shfl_sync(0xFFFFFFFFu, z1[r], src);
            zq[r][i] = (q < 8) ? t0 : t1;
        }
    }

    // ---- anchors: s = sum_p normalize(a_p) in float4 layout ----
    float4 s[R];
    #pragma unroll
    for (int r = 0; r < R; ++r) s[r] = make_float4(0.f, 0.f, 0.f, 0.f);

    // chunk processor: a[r] holds proto (2c+half), dims 4q..4q+3
    #define PROCESS(A)                                                        \
    {                                                                         \
        float nn[R];                                                          \
        _Pragma("unroll")                                                     \
        for (int r = 0; r < R; ++r)                                           \
            nn[r] = A[r].x * A[r].x + A[r].y * A[r].y                         \
                  + A[r].z * A[r].z + A[r].w * A[r].w;                        \
        _Pragma("unroll")                                                     \
        for (int m = 8; m >= 1; m >>= 1) {                                    \
            _Pragma("unroll")                                                 \
            for (int r = 0; r < R; ++r)                                       \
                nn[r] += __shfl_xor_sync(0xFFFFFFFFu, nn[r], m);              \
        }                                                                     \
        _Pragma("unroll")                                                     \
        for (int r = 0; r < R; ++r) {                                         \
            float inv = rsqrtf(fmaxf(nn[r], EPS2));                           \
            s[r].x = fmaf(A[r].x, inv, s[r].x);                               \
            s[r].y = fmaf(A[r].y, inv, s[r].y);                               \
            s[r].z = fmaf(A[r].z, inv, s[r].z);                               \
            s[r].w = fmaf(A[r].w, inv, s[r].w);                               \
        }                                                                     \
    }

    PROCESS(pa0);
    PROCESS(pa1);

    #pragma unroll
    for (int cc = 2; cc < NP / 2; cc += 2) {
        float4 a0[R], a1[R];
        #pragma unroll
        for (int r = 0; r < R; ++r) {
            a0[r] = __ldg((const float4*)(ap[r] + (cc * 2 + half) * D) + q);
            a1[r] = __ldg((const float4*)(ap[r] + ((cc + 1) * 2 + half) * D) + q);
        }
        PROCESS(a0);
        PROCESS(a1);
    }
    #undef PROCESS

    // fold the two halves of s (protos with other parity)
    #pragma unroll
    for (int r = 0; r < R; ++r) {
        s[r].x += __shfl_xor_sync(0xFFFFFFFFu, s[r].x, 16);
        s[r].y += __shfl_xor_sync(0xFFFFFFFFu, s[r].y, 16);
        s[r].z += __shfl_xor_sync(0xFFFFFFFFu, s[r].z, 16);
        s[r].w += __shfl_xor_sync(0xFFFFFFFFu, s[r].w, 16);
    }

    // ---- score = z . s ----
    #pragma unroll
    for (int r = 0; r < R; ++r) {
        float d = zq[r][0] * s[r].x + zq[r][1] * s[r].y
                + zq[r][2] * s[r].z + zq[r][3] * s[r].w;
        #pragma unroll
        for (int m = 8; m >= 1; m >>= 1)
            d += __shfl_xor_sync(0xFFFFFFFFu, d, m);
        if (lane == 0)
            out[rowbase + r] = d;
    }
}

extern "C" void kernel_launch(void* const* d_in, const int* in_sizes, int n_in,
                              void* d_out, int out_size) {
    const int*   uidx  = (const int*)d_in[0];
    const float* x     = (const float*)d_in[1];
    const float* proto = (const float*)d_in[2];
    const float* W     = (const float*)d_in[3];
    const float* b     = (const float*)d_in[4];
    float* out = (float*)d_out;

    user_memory_kernel<<<NBLOCKS, THREADS>>>(uidx, x, proto, W, b, out);
}

// round 4
// speedup vs baseline: 1.5838x; 1.4009x over previous
#include <cuda_runtime.h>
#include <cuda_bf16.h>

#define NP      20
#define D       64
#define NROWS   16384
#define EPS2    1e-24f      // (1e-12)^2 guard under rsqrt

#define R       4                    // rows per warp
#define WPB     8                    // warps per block
#define THREADS (WPB * 32)
#define ROWSB   (WPB * R)            // 32
#define NBLOCKS (NROWS / ROWSB)      // 512

__global__ __launch_bounds__(THREADS, 3)
void user_memory_kernel(const int* __restrict__ uidx,
                        const float* __restrict__ x,
                        const float* __restrict__ proto,
                        const float* __restrict__ W,
                        const float* __restrict__ b,
                        float* __restrict__ out)
{
    __shared__ float Wt[D][D + 2];     // Wt[k][d] = W[d][k]; stride 66
    __shared__ float xs[ROWSB][D];

    const int tid  = threadIdx.x;
    const int warp = tid >> 5;
    const int lane = tid & 31;
    const int q    = lane & 15;        // position within 16-lane half
    const int half = lane >> 4;        // which proto of a pair this half handles

    const int rowbase = (blockIdx.x * WPB + warp) * R;
    const int rlocal  = warp * R;

    // ---- gather pointers + prefetch anchor chunk 0 (protos 0,1) ----
    const float* ap[R];
    #pragma unroll
    for (int r = 0; r < R; ++r) {
        int u = __ldg(&uidx[rowbase + r]);
        ap[r] = proto + (size_t)u * (NP * D);
    }
    float4 cur[R];
    #pragma unroll
    for (int r = 0; r < R; ++r)
        cur[r] = __ldg((const float4*)(ap[r] + half * D) + q);

    // ---- stage W transposed + x rows ----
    #pragma unroll
    for (int i = tid; i < D * D; i += THREADS) {
        int d = i >> 6, k = i & 63;
        Wt[k][d] = W[i];
    }
    #pragma unroll
    for (int r = 0; r < R; ++r) {
        float2 v = ((const float2*)(x + (size_t)(rowbase + r) * D))[lane];
        ((float2*)&xs[rlocal + r][0])[lane] = v;
    }
    __syncthreads();

    // ---- matvec: lane owns dims (2*lane, 2*lane+1) for all R rows ----
    float2 bb = ((const float2*)b)[lane];
    float2 h[R];
    #pragma unroll
    for (int r = 0; r < R; ++r) h[r] = bb;

    #pragma unroll 4
    for (int kq = 0; kq < D / 4; ++kq) {
        float4 x4[R];
        #pragma unroll
        for (int r = 0; r < R; ++r)
            x4[r] = *(const float4*)&xs[rlocal + r][4 * kq];   // broadcast, 1 wf
        #pragma unroll
        for (int j = 0; j < 4; ++j) {
            float2 w = *(const float2*)&Wt[4 * kq + j][2 * lane];  // shared by all rows
            #pragma unroll
            for (int r = 0; r < R; ++r) {
                float xv = (j == 0) ? x4[r].x : (j == 1) ? x4[r].y
                         : (j == 2) ? x4[r].z : x4[r].w;
                h[r].x = fmaf(xv, w.x, h[r].x);
                h[r].y = fmaf(xv, w.y, h[r].y);
            }
        }
    }

    // ---- normalize h -> z (float2 per lane over full warp) ----
    float2 z[R];
    {
        float nn[R];
        #pragma unroll
        for (int r = 0; r < R; ++r) nn[r] = h[r].x * h[r].x + h[r].y * h[r].y;
        #pragma unroll
        for (int m = 16; m >= 1; m >>= 1) {
            #pragma unroll
            for (int r = 0; r < R; ++r)
                nn[r] += __shfl_xor_sync(0xFFFFFFFFu, nn[r], m);
        }
        #pragma unroll
        for (int r = 0; r < R; ++r) {
            float inv = rsqrtf(fmaxf(nn[r], EPS2));
            z[r].x = h[r].x * inv;
            z[r].y = h[r].y * inv;
        }
    }

    // ---- permute z into float4 layout: zq[r] = z[dims 4q..4q+3] ----
    float4 zq[R];
    #pragma unroll
    for (int r = 0; r < R; ++r) {
        zq[r].x = __shfl_sync(0xFFFFFFFFu, z[r].x, 2 * q);
        zq[r].y = __shfl_sync(0xFFFFFFFFu, z[r].y, 2 * q);
        zq[r].z = __shfl_sync(0xFFFFFFFFu, z[r].x, 2 * q + 1);
        zq[r].w = __shfl_sync(0xFFFFFFFFu, z[r].y, 2 * q + 1);
    }

    // ---- anchors: s = sum_p normalize(a_p); 2 protos per warp-instruction ----
    float4 s[R];
    #pragma unroll
    for (int r = 0; r < R; ++r) s[r] = make_float4(0.f, 0.f, 0.f, 0.f);

    #define PROCESS(A)                                                        \
    {                                                                         \
        float nn[R];                                                          \
        _Pragma("unroll")                                                     \
        for (int r = 0; r < R; ++r)                                           \
            nn[r] = A[r].x * A[r].x + A[r].y * A[r].y                         \
                  + A[r].z * A[r].z + A[r].w * A[r].w;                        \
        _Pragma("unroll")                                                     \
        for (int m = 8; m >= 1; m >>= 1) {                                    \
            _Pragma("unroll")                                                 \
            for (int r = 0; r < R; ++r)                                       \
                nn[r] += __shfl_xor_sync(0xFFFFFFFFu, nn[r], m);              \
        }                                                                     \
        _Pragma("unroll")                                                     \
        for (int r = 0; r < R; ++r) {                                         \
            float inv = rsqrtf(fmaxf(nn[r], EPS2));                           \
            s[r].x = fmaf(A[r].x, inv, s[r].x);                               \
            s[r].y = fmaf(A[r].y, inv, s[r].y);                               \
            s[r].z = fmaf(A[r].z, inv, s[r].z);                               \
            s[r].w = fmaf(A[r].w, inv, s[r].w);                               \
        }                                                                     \
    }

    // software-pipelined chunk loop: chunk c = protos (2c, 2c+1)
    #pragma unroll
    for (int c = 0; c < NP / 2; ++c) {
        float4 nxt[R];
        if (c + 1 < NP / 2) {
            #pragma unroll
            for (int r = 0; r < R; ++r)
                nxt[r] = __ldg((const float4*)(ap[r] + ((c + 1) * 2 + half) * D) + q);
        }
        PROCESS(cur);
        #pragma unroll
        for (int r = 0; r < R; ++r) cur[r] = nxt[r];
    }
    #undef PROCESS

    // fold the two halves of s (other proto parity)
    #pragma unroll
    for (int r = 0; r < R; ++r) {
        s[r].x += __shfl_xor_sync(0xFFFFFFFFu, s[r].x, 16);
        s[r].y += __shfl_xor_sync(0xFFFFFFFFu, s[r].y, 16);
        s[r].z += __shfl_xor_sync(0xFFFFFFFFu, s[r].z, 16);
        s[r].w += __shfl_xor_sync(0xFFFFFFFFu, s[r].w, 16);
    }

    // ---- score = z . s ----
    #pragma unroll
    for (int r = 0; r < R; ++r) {
        float d = zq[r].x * s[r].x + zq[r].y * s[r].y
                + zq[r].z * s[r].z + zq[r].w * s[r].w;
        #pragma unroll
        for (int m = 8; m >= 1; m >>= 1)
            d += __shfl_xor_sync(0xFFFFFFFFu, d, m);
        if (lane == 0)
            out[rowbase + r] = d;
    }
}

extern "C" void kernel_launch(void* const* d_in, const int* in_sizes, int n_in,
                              void* d_out, int out_size) {
    const int*   uidx  = (const int*)d_in[0];
    const float* x     = (const float*)d_in[1];
    const float* proto = (const float*)d_in[2];
    const float* W     = (const float*)d_in[3];
    const float* b     = (const float*)d_in[4];
    float* out = (float*)d_out;

    user_memory_kernel<<<NBLOCKS, THREADS>>>(uidx, x, proto, W, b, out);
}